// round 9
// baseline (speedup 1.0000x reference)
#include <cuda_runtime.h>
#include <cstdint>

// ---------------------------------------------------------------------------
// StructureEmbeddingLayer  B=128, N=48, E=64, D=256, M=49
// ---------------------------------------------------------------------------

typedef unsigned long long U64;

// ---- packed f32x2 helpers (sm_100+) ----
__device__ __forceinline__ U64 f2pk(float lo, float hi) {
    U64 r;
    asm("mov.b64 %0, {%1, %2};" : "=l"(r)
        : "r"(__float_as_uint(lo)), "r"(__float_as_uint(hi)));
    return r;
}
__device__ __forceinline__ void f2un(U64 v, float& lo, float& hi) {
    unsigned a, b;
    asm("mov.b64 {%0, %1}, %2;" : "=r"(a), "=r"(b) : "l"(v));
    lo = __uint_as_float(a); hi = __uint_as_float(b);
}
__device__ __forceinline__ U64 f2dup(float x) { return f2pk(x, x); }
__device__ __forceinline__ U64 f2add(U64 a, U64 b) {
    U64 r; asm("add.rn.f32x2 %0, %1, %2;" : "=l"(r) : "l"(a), "l"(b)); return r;
}
__device__ __forceinline__ U64 f2mul(U64 a, U64 b) {
    U64 r; asm("mul.rn.f32x2 %0, %1, %2;" : "=l"(r) : "l"(a), "l"(b)); return r;
}
__device__ __forceinline__ U64 f2fma(U64 a, U64 b, U64 c) {
    U64 r; asm("fma.rn.f32x2 %0, %1, %2, %3;" : "=l"(r) : "l"(a), "l"(b), "l"(c)); return r;
}

// butterfly warp sum (redux.f32 is NOT supported on sm_103)
__device__ __forceinline__ float warp_sum(float v) {
#pragma unroll
    for (int o = 16; o; o >>= 1) v += __shfl_xor_sync(0xffffffffu, v, o);
    return v;
}

// ---- scratch (no cudaMalloc allowed) ----
__device__ float g_hb   [8192 * 256];   // masked bond embedding  [B*E, D]
__device__ float g_rev  [8192 * 256];   // hb @ W_rev + b_rev     [B*E, D]
__device__ float g_tsc_c[44 * 256];     // row-centered table_sc
__device__ float g_wsf_c[8 * 256];      // row-centered W_sf
__device__ float g_bsf_c[256];          // centered b_sf

// ===========================================================================
// Kernel 0: center rows of table_sc / W_sf / b_sf (makes LN means exactly 0)
// ===========================================================================
__global__ void __launch_bounds__(256) center_kernel(
    const float* __restrict__ tsc, const float* __restrict__ Wsf,
    const float* __restrict__ bsf)
{
    __shared__ float red[8];
    const int blk = blockIdx.x, t = threadIdx.x;
    const float* src; float* dst;
    if (blk < 44)      { src = tsc + blk * 256;        dst = g_tsc_c + blk * 256; }
    else if (blk < 52) { src = Wsf + (blk - 44) * 256; dst = g_wsf_c + (blk - 44) * 256; }
    else               { src = bsf;                    dst = g_bsf_c; }
    float v = __ldg(src + t);
    float s = warp_sum(v);
    if ((t & 31) == 0) red[t >> 5] = s;
    __syncthreads();
    float tot = 0.f;
#pragma unroll
    for (int k = 0; k < 8; k++) tot += red[k];
    dst[t] = v - tot * (1.0f / 256.0f);
}

// ===========================================================================
// Kernel 1: per-bond embedding hb  (grid B*E = 8192, block 256)
// ===========================================================================
__device__ __forceinline__ void stats256(float x, float* red, float& mu, float& rs) {
    float sx = x, sq = x * x;
#pragma unroll
    for (int o = 16; o; o >>= 1) {
        sx += __shfl_xor_sync(0xffffffffu, sx, o);
        sq += __shfl_xor_sync(0xffffffffu, sq, o);
    }
    int w = threadIdx.x >> 5;
    __syncthreads();
    if ((threadIdx.x & 31) == 0) { red[w] = sx; red[8 + w] = sq; }
    __syncthreads();
    float tx = 0.f, tq = 0.f;
#pragma unroll
    for (int k = 0; k < 8; k++) { tx += red[k]; tq += red[8 + k]; }
    mu = tx * (1.0f / 256.0f);
    rs = rsqrtf(fmaf(tq, 1.0f / 256.0f, -mu * mu) + 1e-5f);
}

__global__ void __launch_bounds__(256) hb_kernel(
    const int*   __restrict__ bfc,   // [B,E,3]
    const float* __restrict__ bff,   // [B,E,4]
    const float* __restrict__ mask,  // [B,E]
    const float* __restrict__ tbc,   // [33,256]
    const float* __restrict__ g1, const float* __restrict__ b1,
    const float* __restrict__ Wbf,   // [4,256]
    const float* __restrict__ bbf,
    const float* __restrict__ g2, const float* __restrict__ b2)
{
    __shared__ float red[16];
    const int be = blockIdx.x;
    const int d  = threadIdx.x;

    const int c0 = __ldg(bfc + be * 3 + 0) + 1;       // starts_bc = {0,11,22}, +1
    const int c1 = __ldg(bfc + be * 3 + 1) + 12;
    const int c2 = __ldg(bfc + be * 3 + 2) + 23;
    float xc = __ldg(tbc + c0 * 256 + d)
             + __ldg(tbc + c1 * 256 + d)
             + __ldg(tbc + c2 * 256 + d);
    float mu, rs;
    stats256(xc, red, mu, rs);
    float lnc = (xc - mu) * rs * __ldg(g1 + d) + __ldg(b1 + d);

    const float x0 = __ldg(bff + be * 4 + 0);
    const float x1 = __ldg(bff + be * 4 + 1);
    const float x2 = __ldg(bff + be * 4 + 2);
    const float x3 = __ldg(bff + be * 4 + 3);
    float xp = __ldg(bbf + d)
             + x0 * __ldg(Wbf + d)
             + x1 * __ldg(Wbf + 256 + d)
             + x2 * __ldg(Wbf + 512 + d)
             + x3 * __ldg(Wbf + 768 + d);
    float mu2, rs2;
    stats256(xp, red, mu2, rs2);
    float lnp = (xp - mu2) * rs2 * __ldg(g2 + d) + __ldg(b2 + d);

    g_hb[be * 256 + d] = (lnc + lnp) * __ldg(mask + be);
}

// ===========================================================================
// Kernel 2: g_rev = g_hb @ W_rev + b_rev   (8192x256 @ 256x256)
// ===========================================================================
__global__ void __launch_bounds__(256) rev_kernel(
    const float* __restrict__ Wrev,   // [256,256]
    const float* __restrict__ brev)   // [256]
{
    constexpr int RROWS = 16, RPAD = 20;
    __shared__ __align__(16) float As[256 * RPAD];

    const int row0 = blockIdx.x * RROWS;
    const int t = threadIdx.x;

    for (int idx = t; idx < 256 * RROWS; idx += 256) {
        int r = idx >> 8;
        int k = idx & 255;
        As[k * RPAD + r] = g_hb[(row0 + r) * 256 + k];
    }
    __syncthreads();

    U64 acc[8];
#pragma unroll
    for (int p = 0; p < 8; p++) acc[p] = 0ULL;

#pragma unroll 4
    for (int k = 0; k < 256; k++) {
        U64 wd = f2dup(__ldg(Wrev + k * 256 + t));
        const ulonglong2* ap = (const ulonglong2*)(As + k * RPAD);
#pragma unroll
        for (int q = 0; q < 4; q++) {
            ulonglong2 a = ap[q];
            acc[2 * q]     = f2fma(a.x, wd, acc[2 * q]);
            acc[2 * q + 1] = f2fma(a.y, wd, acc[2 * q + 1]);
        }
    }

    const float bv = __ldg(brev + t);
#pragma unroll
    for (int p = 0; p < 8; p++) {
        float lo, hi; f2un(acc[p], lo, hi);
        g_rev[(row0 + 2 * p)     * 256 + t] = lo + bv;
        g_rev[(row0 + 2 * p + 1) * 256 + t] = hi + bv;
    }
}

// ===========================================================================
// Kernel 3: virtual-edge rows/cols (pure bandwidth)
// ===========================================================================
__global__ void __launch_bounds__(256) ve_kernel(
    const float4* __restrict__ vev,   // [64] float4 view of ve[256]
    float4* __restrict__ out)
{
    const int stride = gridDim.x * 256;
    const int total = 128 * 97 * 64;          // float4 units
    for (int t = blockIdx.x * 256 + threadIdx.x; t < total; t += stride) {
        int d4 = t & 63;
        int r = t >> 6;                        // 0 .. 128*97-1
        int b = r / 97;
        int pos = r - b * 97;                  // 0..48: (0,j)   49..96: (i,0)
        size_t cell = (size_t)b * 2401 + (pos < 49 ? pos : (size_t)(pos - 48) * 49);
        out[cell * 64 + d4] = __ldg(vev + d4);
    }
}

// ===========================================================================
// Kernel 4: interior fill. Warp per pair, contiguous per-warp chunks.
//   Software-pipelined across pairs: the SHFL reduction of pair k overlaps
//   the table-gather + projection of pair k+1 (dual register sets).
//   Lane owns d = {4L..4L+3} U {128+4L..128+4L+3}.
// ===========================================================================
__device__ __forceinline__ void load4(const float* __restrict__ p, int lane, U64 v[4]) {
    float4 a = __ldg((const float4*)p + lane);
    float4 b = __ldg((const float4*)p + 32 + lane);
    v[0] = f2pk(a.x, a.y); v[1] = f2pk(a.z, a.w);
    v[2] = f2pk(b.x, b.y); v[3] = f2pk(b.z, b.w);
}

// gather 4 centered table rows + centered 8->256 projection for one pair
__device__ __forceinline__ void gather_project(
    const ulonglong2* __restrict__ tb, int lane,
    int4 ci, float4 x0, float4 x1,
    const U64 wsf[8][4], const U64 bc[4],
    U64 c[4], U64 p[4])
{
    {
        int r = (ci.x + 1) * 64;
        ulonglong2 t = tb[r + lane];       c[0] = t.x; c[1] = t.y;
        t = tb[r + 32 + lane];             c[2] = t.x; c[3] = t.y;
    }
    {
        int r = (ci.y + 12) * 64;
        ulonglong2 t = tb[r + lane];       c[0] = f2add(c[0], t.x); c[1] = f2add(c[1], t.y);
        t = tb[r + 32 + lane];             c[2] = f2add(c[2], t.x); c[3] = f2add(c[3], t.y);
    }
    {
        int r = (ci.z + 23) * 64;
        ulonglong2 t = tb[r + lane];       c[0] = f2add(c[0], t.x); c[1] = f2add(c[1], t.y);
        t = tb[r + 32 + lane];             c[2] = f2add(c[2], t.x); c[3] = f2add(c[3], t.y);
    }
    {
        int r = (ci.w + 34) * 64;
        ulonglong2 t = tb[r + lane];       c[0] = f2add(c[0], t.x); c[1] = f2add(c[1], t.y);
        t = tb[r + 32 + lane];             c[2] = f2add(c[2], t.x); c[3] = f2add(c[3], t.y);
    }
    p[0] = bc[0]; p[1] = bc[1]; p[2] = bc[2]; p[3] = bc[3];
    const float xv[8] = { x0.x, x0.y, x0.z, x0.w, x1.x, x1.y, x1.z, x1.w };
#pragma unroll
    for (int f = 0; f < 8; f++) {
        U64 xd = f2dup(xv[f]);
        p[0] = f2fma(wsf[f][0], xd, p[0]);
        p[1] = f2fma(wsf[f][1], xd, p[1]);
        p[2] = f2fma(wsf[f][2], xd, p[2]);
        p[3] = f2fma(wsf[f][3], xd, p[3]);
    }
}

__global__ void __launch_bounds__(128, 3) fill_kernel(
    const int4*   __restrict__ sfc,   // [B*48*48] int4
    const float4* __restrict__ sff,   // [B*48*48*2] float4
    const float*  __restrict__ gsc_p, const float* __restrict__ bsc_p,
    const float*  __restrict__ gsf_p, const float* __restrict__ bsf_ln,
    float* __restrict__ out)
{
    __shared__ __align__(16) float s_tab[44 * 256];

    const int tid = threadIdx.x;
    {   // stage centered table via float4
        const float4* src = (const float4*)g_tsc_c;
        float4* dst = (float4*)s_tab;
        for (int idx = tid; idx < 44 * 64; idx += 128) dst[idx] = src[idx];
    }
    __syncthreads();

    const int lane = tid & 31;
    const int warp = tid >> 5;

    U64 gsc[4], gsf[4], bsum[4], bc[4], wsf[8][4];
    load4(gsc_p, lane, gsc);
    load4(gsf_p, lane, gsf);
    {
        U64 t1[4], t2[4];
        load4(bsc_p, lane, t1);
        load4(bsf_ln, lane, t2);
#pragma unroll
        for (int p = 0; p < 4; p++) bsum[p] = f2add(t1[p], t2[p]);
    }
    load4(g_bsf_c, lane, bc);
#pragma unroll
    for (int f = 0; f < 8; f++) load4(g_wsf_c + f * 256, lane, wsf[f]);

    const ulonglong2* tb = (const ulonglong2*)s_tab;

    const int TOT = 128 * 48 * 48;
    const int NW = gridDim.x * 4;
    const int gw = blockIdx.x * 4 + warp;
    const int chunk = (TOT + NW - 1) / NW;
    int q = gw * chunk;
    int qend = q + chunk; if (qend > TOT) qend = TOT;
    if (q >= qend) return;

    // incremental (b,i,j) decode + dst pointer
    int b = q / 2304;
    int rem = q - b * 2304;
    int i = rem / 48;
    int j = rem - i * 48;
    float* dst = out + ((size_t)((b * 49 + i + 1) * 49 + (j + 1))) * 256;

    // ---- prologue: gather+project pair q ----
    U64 c[4], p[4];
    {
        int4   ci = __ldg(sfc + q);
        float4 x0 = __ldg(sff + 2 * q);
        float4 x1 = __ldg(sff + 2 * q + 1);
        gather_project(tb, lane, ci, x0, x1, wsf, bc, c, p);
    }

    while (q < qend) {
        // ---- start the long-latency reduction for the CURRENT pair ----
        U64 qc = f2fma(c[0], c[0], f2fma(c[1], c[1], f2fma(c[2], c[2], f2mul(c[3], c[3]))));
        U64 qp = f2fma(p[0], p[0], f2fma(p[1], p[1], f2fma(p[2], p[2], f2mul(p[3], p[3]))));
        float qcl, qch, qpl, qph;
        f2un(qc, qcl, qch); f2un(qp, qpl, qph);
        float sc = qcl + qch, sp = qpl + qph;
#pragma unroll
        for (int o = 16; o; o >>= 1) {
            sc += __shfl_xor_sync(0xffffffffu, sc, o);
            sp += __shfl_xor_sync(0xffffffffu, sp, o);
        }

        // ---- overlap: gather+project the NEXT pair while shuffles drain ----
        const int qn = q + 1;
        U64 cn[4], pn[4];
        if (qn < qend) {
            int4   ci = __ldg(sfc + qn);
            float4 x0 = __ldg(sff + 2 * qn);
            float4 x1 = __ldg(sff + 2 * qn + 1);
            if (qn + 8 < TOT) {
                asm volatile("prefetch.global.L2 [%0];" :: "l"(sfc + qn + 8));
                asm volatile("prefetch.global.L2 [%0];" :: "l"(sff + 2 * (qn + 8)));
            }
            gather_project(tb, lane, ci, x0, x1, wsf, bc, cn, pn);
        }

        // ---- finish current pair: rsqrt, scale, store ----
        const float rs_c = rsqrtf(fmaf(sc, 1.0f / 256.0f, 1e-5f));
        const float rs_p = rsqrtf(fmaf(sp, 1.0f / 256.0f, 1e-5f));
        const U64 rc = f2dup(rs_c), rp = f2dup(rs_p);

        U64 o0 = f2fma(c[0], f2mul(gsc[0], rc), bsum[0]); o0 = f2fma(p[0], f2mul(gsf[0], rp), o0);
        U64 o1 = f2fma(c[1], f2mul(gsc[1], rc), bsum[1]); o1 = f2fma(p[1], f2mul(gsf[1], rp), o1);
        U64 o2 = f2fma(c[2], f2mul(gsc[2], rc), bsum[2]); o2 = f2fma(p[2], f2mul(gsf[2], rp), o2);
        U64 o3 = f2fma(c[3], f2mul(gsc[3], rc), bsum[3]); o3 = f2fma(p[3], f2mul(gsf[3], rp), o3);

        ulonglong2* dv = (ulonglong2*)dst;
        ulonglong2 w01; w01.x = o0; w01.y = o1;
        ulonglong2 w23; w23.x = o2; w23.y = o3;
        dv[lane]      = w01;
        dv[32 + lane] = w23;

        // rotate pipeline registers
#pragma unroll
        for (int k = 0; k < 4; k++) { c[k] = cn[k]; p[k] = pn[k]; }

        // advance
        q = qn;
        dst += 256;
        if (++j == 48) {
            j = 0; dst += 256;                 // skip (i+1, 0)
            if (++i == 48) { i = 0; dst += 49 * 256; }   // skip row (b+1, 0, :)
        }
    }
}

// ===========================================================================
// Kernel 5: scatter-add bonds with vectorized red.global (v4.f32).
//   grid 8192 (bond), block 128: lanes 0-63 add hb into (i0,i1),
//   lanes 64-127 add rev into (i1,i0).  4x fewer REDG lanes than scalar.
// ===========================================================================
__global__ void __launch_bounds__(128) scatter_kernel(
    const int* __restrict__ bidx,    // [B,2,E]
    float* __restrict__ out)
{
    const int be = blockIdx.x;
    const int b = be >> 6, e = be & 63;
    const int t = threadIdx.x;
    const int d4 = t & 63;                     // float4 index 0..63
    const bool fwd = t < 64;

    const int i0 = __ldg(bidx + (b * 2)     * 64 + e) + 1;
    const int i1 = __ldg(bidx + (b * 2 + 1) * 64 + e) + 1;

    const float4* src = (const float4*)(fwd ? g_hb : g_rev) + be * 64 + d4;
    const float4 v = *src;

    const size_t cell = fwd ? ((size_t)(b * 49 + i0) * 49 + i1)
                            : ((size_t)(b * 49 + i1) * 49 + i0);
    float* p = out + cell * 256 + d4 * 4;
    asm volatile("red.global.add.v4.f32 [%0], {%1, %2, %3, %4};"
                 :: "l"(p), "f"(v.x), "f"(v.y), "f"(v.z), "f"(v.w)
                 : "memory");
}

// ===========================================================================
extern "C" void kernel_launch(void* const* d_in, const int* in_sizes, int n_in,
                              void* d_out, int out_size)
{
    (void)in_sizes; (void)n_in; (void)out_size;

    const int*    bond_index = (const int*)   d_in[0];
    const int*    bfc        = (const int*)   d_in[1];
    const float*  bff        = (const float*) d_in[2];
    const float*  bmask      = (const float*) d_in[3];
    const int4*   sfc        = (const int4*)  d_in[4];
    const float4* sff        = (const float4*)d_in[5];
    const float*  tbc        = (const float*) d_in[6];
    const float*  ln_bc_g    = (const float*) d_in[7];
    const float*  ln_bc_b    = (const float*) d_in[8];
    const float*  W_bf       = (const float*) d_in[9];
    const float*  b_bf       = (const float*) d_in[10];
    const float*  ln_bf_g    = (const float*) d_in[11];
    const float*  ln_bf_b    = (const float*) d_in[12];
    const float*  tsc        = (const float*) d_in[13];
    const float*  ln_sc_g    = (const float*) d_in[14];
    const float*  ln_sc_b    = (const float*) d_in[15];
    const float*  W_sf       = (const float*) d_in[16];
    const float*  b_sf       = (const float*) d_in[17];
    const float*  ln_sf_g    = (const float*) d_in[18];
    const float*  ln_sf_b    = (const float*) d_in[19];
    const float*  ve         = (const float*) d_in[20];
    const float*  W_rev      = (const float*) d_in[21];
    const float*  b_rev      = (const float*) d_in[22];
    float* out = (float*)d_out;

    center_kernel<<<53, 256>>>(tsc, W_sf, b_sf);
    hb_kernel<<<8192, 256>>>(bfc, bff, bmask, tbc, ln_bc_g, ln_bc_b,
                             W_bf, b_bf, ln_bf_g, ln_bf_b);
    rev_kernel<<<512, 256>>>(W_rev, b_rev);
    ve_kernel<<<592, 256>>>((const float4*)ve, (float4*)out);
    fill_kernel<<<444, 128>>>(sfc, sff, ln_sc_g, ln_sc_b,
                              ln_sf_g, ln_sf_b, out);
    scatter_kernel<<<8192, 128>>>(bond_index, out);
}

// round 10
// speedup vs baseline: 1.0674x; 1.0674x over previous
#include <cuda_runtime.h>
#include <cstdint>

// ---------------------------------------------------------------------------
// StructureEmbeddingLayer  B=128, N=48, E=64, D=256, M=49
// ---------------------------------------------------------------------------

typedef unsigned long long U64;

// ---- packed f32x2 helpers (sm_100+) ----
__device__ __forceinline__ U64 f2pk(float lo, float hi) {
    U64 r;
    asm("mov.b64 %0, {%1, %2};" : "=l"(r)
        : "r"(__float_as_uint(lo)), "r"(__float_as_uint(hi)));
    return r;
}
__device__ __forceinline__ void f2un(U64 v, float& lo, float& hi) {
    unsigned a, b;
    asm("mov.b64 {%0, %1}, %2;" : "=r"(a), "=r"(b) : "l"(v));
    lo = __uint_as_float(a); hi = __uint_as_float(b);
}
__device__ __forceinline__ U64 f2dup(float x) { return f2pk(x, x); }
__device__ __forceinline__ U64 f2add(U64 a, U64 b) {
    U64 r; asm("add.rn.f32x2 %0, %1, %2;" : "=l"(r) : "l"(a), "l"(b)); return r;
}
__device__ __forceinline__ U64 f2mul(U64 a, U64 b) {
    U64 r; asm("mul.rn.f32x2 %0, %1, %2;" : "=l"(r) : "l"(a), "l"(b)); return r;
}
__device__ __forceinline__ U64 f2fma(U64 a, U64 b, U64 c) {
    U64 r; asm("fma.rn.f32x2 %0, %1, %2, %3;" : "=l"(r) : "l"(a), "l"(b), "l"(c)); return r;
}

__device__ __forceinline__ float warp_sum(float v) {
#pragma unroll
    for (int o = 16; o; o >>= 1) v += __shfl_xor_sync(0xffffffffu, v, o);
    return v;
}

// ---- scratch (no cudaMalloc allowed) ----
__device__ float  g_hb   [8192 * 256];   // masked bond embedding  [B*E, D]
__device__ float  g_rev  [8192 * 256];   // hb @ W_rev + b_rev     [B*E, D]
__device__ float  g_tsc_c[44 * 256];     // row-centered table_sc
__device__ float  g_wsf_c[8 * 256];      // row-centered W_sf
__device__ float  g_bsf_c[256];          // centered b_sf
__device__ float  g_dotc [600];          // cross-slice dot tables (6 x 10 x 10)
__device__ float  g_norm [40];           // per-used-row squared norms
__device__ float  g_G    [64];           // W_c W_c^T (8x8)
__device__ float  g_v    [8];            // W_c . b_c
__device__ float  g_n0   [1];            // ||b_c||^2
__device__ float2 g_rs   [128 * 48 * 48]; // per-pair (rs_c, rs_p)

// ===========================================================================
// Kernel 0: center rows of table_sc / W_sf / b_sf (makes LN means exactly 0)
// ===========================================================================
__global__ void __launch_bounds__(256) center_kernel(
    const float* __restrict__ tsc, const float* __restrict__ Wsf,
    const float* __restrict__ bsf)
{
    __shared__ float red[8];
    const int blk = blockIdx.x, t = threadIdx.x;
    const float* src; float* dst;
    if (blk < 44)      { src = tsc + blk * 256;        dst = g_tsc_c + blk * 256; }
    else if (blk < 52) { src = Wsf + (blk - 44) * 256; dst = g_wsf_c + (blk - 44) * 256; }
    else               { src = bsf;                    dst = g_bsf_c; }
    float v = __ldg(src + t);
    float s = warp_sum(v);
    if ((t & 31) == 0) red[t >> 5] = s;
    __syncthreads();
    float tot = 0.f;
#pragma unroll
    for (int k = 0; k < 8; k++) tot += red[k];
    dst[t] = v - tot * (1.0f / 256.0f);
}

// ===========================================================================
// Kernel 0b: all dot products needed for precomputed variances.
//   jobs 0..599   : cross-slice dots (6 combos x 10 x 10)
//   jobs 600..639 : squared norms of the 40 used table rows
//   jobs 640..703 : G[i][j] = Wc_i . Wc_j
//   jobs 704..711 : v[i]    = Wc_i . b_c
//   job  712      : n0      = b_c . b_c
// ===========================================================================
__global__ void __launch_bounds__(256) dots_kernel()
{
    const int job = blockIdx.x * 8 + (threadIdx.x >> 5);
    const int lane = threadIdx.x & 31;
    if (job >= 713) return;
    const float *v1, *v2; float* dst;
    if (job < 600) {
        int combo = job / 100, ij = job % 100, i = ij / 10, jj = ij % 10;
        int r1, r2;
        switch (combo) {
            case 0:  r1 = 1 + i;  r2 = 12 + jj; break;   // A,B
            case 1:  r1 = 23 + i; r2 = 34 + jj; break;   // C,D
            case 2:  r1 = 1 + i;  r2 = 23 + jj; break;   // A,C
            case 3:  r1 = 1 + i;  r2 = 34 + jj; break;   // A,D
            case 4:  r1 = 12 + i; r2 = 23 + jj; break;   // B,C
            default: r1 = 12 + i; r2 = 34 + jj; break;   // B,D
        }
        v1 = g_tsc_c + r1 * 256; v2 = g_tsc_c + r2 * 256; dst = g_dotc + job;
    } else if (job < 640) {
        int jn = job - 600;
        int row = (jn / 10) * 11 + 1 + (jn % 10);
        v1 = v2 = g_tsc_c + row * 256; dst = g_norm + jn;
    } else if (job < 704) {
        int i = (job - 640) >> 3, jj = (job - 640) & 7;
        v1 = g_wsf_c + i * 256; v2 = g_wsf_c + jj * 256; dst = g_G + (job - 640);
    } else if (job < 712) {
        v1 = g_wsf_c + (job - 704) * 256; v2 = g_bsf_c; dst = g_v + (job - 704);
    } else {
        v1 = v2 = g_bsf_c; dst = g_n0;
    }
    float s = 0.f;
#pragma unroll
    for (int k = lane; k < 256; k += 32) s += v1[k] * v2[k];
    s = warp_sum(s);
    if (lane == 0) *dst = s;
}

// ===========================================================================
// Kernel 0c: per-pair rstd pre-pass. One thread per pair; pure scalar math.
// ===========================================================================
__global__ void __launch_bounds__(256) rs_kernel(
    const int4* __restrict__ sfc, const float4* __restrict__ sff)
{
    __shared__ float sQ[600];
    __shared__ float sG[64], sv2[8];
    __shared__ float sn0;
    const int t = threadIdx.x;
    for (int idx = t; idx < 600; idx += 256) {
        float val = g_dotc[idx] * 2.f;
        int combo = idx / 100, ij = idx % 100, i = ij / 10, jj = ij % 10;
        if (combo == 0)      val += g_norm[i]      + g_norm[10 + jj];
        else if (combo == 1) val += g_norm[20 + i] + g_norm[30 + jj];
        sQ[idx] = val;
    }
    if (t < 64) sG[t] = g_G[t];
    if (t < 8)  sv2[t] = 2.f * g_v[t];
    if (t == 0) sn0 = g_n0[0];
    __syncthreads();

    const int TOT = 128 * 48 * 48;
    for (int q = blockIdx.x * 256 + t; q < TOT; q += gridDim.x * 256) {
        const int4   ci = __ldg(sfc + q);
        const float4 x0 = __ldg(sff + 2 * q);
        const float4 x1 = __ldg(sff + 2 * q + 1);
        float sc = sQ[ci.x * 10 + ci.y]       + sQ[100 + ci.z * 10 + ci.w]
                 + sQ[200 + ci.x * 10 + ci.z] + sQ[300 + ci.x * 10 + ci.w]
                 + sQ[400 + ci.y * 10 + ci.z] + sQ[500 + ci.y * 10 + ci.w];
        const float xv[8] = { x0.x, x0.y, x0.z, x0.w, x1.x, x1.y, x1.z, x1.w };
        float sp = sn0;
#pragma unroll
        for (int a = 0; a < 8; a++) {
            float y = sv2[a];
#pragma unroll
            for (int b = 0; b < 8; b++) y = fmaf(sG[a * 8 + b], xv[b], y);
            sp = fmaf(xv[a], y, sp);
        }
        float2 rs;
        rs.x = rsqrtf(fmaf(sc, 1.0f / 256.0f, 1e-5f));
        rs.y = rsqrtf(fmaf(sp, 1.0f / 256.0f, 1e-5f));
        g_rs[q] = rs;
    }
}

// ===========================================================================
// Kernel 1: per-bond embedding hb  (grid B*E = 8192, block 256)
// ===========================================================================
__device__ __forceinline__ void stats256(float x, float* red, float& mu, float& rs) {
    float sx = x, sq = x * x;
#pragma unroll
    for (int o = 16; o; o >>= 1) {
        sx += __shfl_xor_sync(0xffffffffu, sx, o);
        sq += __shfl_xor_sync(0xffffffffu, sq, o);
    }
    int w = threadIdx.x >> 5;
    __syncthreads();
    if ((threadIdx.x & 31) == 0) { red[w] = sx; red[8 + w] = sq; }
    __syncthreads();
    float tx = 0.f, tq = 0.f;
#pragma unroll
    for (int k = 0; k < 8; k++) { tx += red[k]; tq += red[8 + k]; }
    mu = tx * (1.0f / 256.0f);
    rs = rsqrtf(fmaf(tq, 1.0f / 256.0f, -mu * mu) + 1e-5f);
}

__global__ void __launch_bounds__(256) hb_kernel(
    const int*   __restrict__ bfc,
    const float* __restrict__ bff,
    const float* __restrict__ mask,
    const float* __restrict__ tbc,
    const float* __restrict__ g1, const float* __restrict__ b1,
    const float* __restrict__ Wbf,
    const float* __restrict__ bbf,
    const float* __restrict__ g2, const float* __restrict__ b2)
{
    __shared__ float red[16];
    const int be = blockIdx.x;
    const int d  = threadIdx.x;

    const int c0 = __ldg(bfc + be * 3 + 0) + 1;
    const int c1 = __ldg(bfc + be * 3 + 1) + 12;
    const int c2 = __ldg(bfc + be * 3 + 2) + 23;
    float xc = __ldg(tbc + c0 * 256 + d)
             + __ldg(tbc + c1 * 256 + d)
             + __ldg(tbc + c2 * 256 + d);
    float mu, rs;
    stats256(xc, red, mu, rs);
    float lnc = (xc - mu) * rs * __ldg(g1 + d) + __ldg(b1 + d);

    const float x0 = __ldg(bff + be * 4 + 0);
    const float x1 = __ldg(bff + be * 4 + 1);
    const float x2 = __ldg(bff + be * 4 + 2);
    const float x3 = __ldg(bff + be * 4 + 3);
    float xp = __ldg(bbf + d)
             + x0 * __ldg(Wbf + d)
             + x1 * __ldg(Wbf + 256 + d)
             + x2 * __ldg(Wbf + 512 + d)
             + x3 * __ldg(Wbf + 768 + d);
    float mu2, rs2;
    stats256(xp, red, mu2, rs2);
    float lnp = (xp - mu2) * rs2 * __ldg(g2 + d) + __ldg(b2 + d);

    g_hb[be * 256 + d] = (lnc + lnp) * __ldg(mask + be);
}

// ===========================================================================
// Kernel 2: g_rev = g_hb @ W_rev + b_rev   (8192x256 @ 256x256)
// ===========================================================================
__global__ void __launch_bounds__(256) rev_kernel(
    const float* __restrict__ Wrev,
    const float* __restrict__ brev)
{
    constexpr int RROWS = 16, RPAD = 20;
    __shared__ __align__(16) float As[256 * RPAD];

    const int row0 = blockIdx.x * RROWS;
    const int t = threadIdx.x;

    for (int idx = t; idx < 256 * RROWS; idx += 256) {
        int r = idx >> 8;
        int k = idx & 255;
        As[k * RPAD + r] = g_hb[(row0 + r) * 256 + k];
    }
    __syncthreads();

    U64 acc[8];
#pragma unroll
    for (int p = 0; p < 8; p++) acc[p] = 0ULL;

#pragma unroll 4
    for (int k = 0; k < 256; k++) {
        U64 wd = f2dup(__ldg(Wrev + k * 256 + t));
        const ulonglong2* ap = (const ulonglong2*)(As + k * RPAD);
#pragma unroll
        for (int q = 0; q < 4; q++) {
            ulonglong2 a = ap[q];
            acc[2 * q]     = f2fma(a.x, wd, acc[2 * q]);
            acc[2 * q + 1] = f2fma(a.y, wd, acc[2 * q + 1]);
        }
    }

    const float bv = __ldg(brev + t);
#pragma unroll
    for (int p = 0; p < 8; p++) {
        float lo, hi; f2un(acc[p], lo, hi);
        g_rev[(row0 + 2 * p)     * 256 + t] = lo + bv;
        g_rev[(row0 + 2 * p + 1) * 256 + t] = hi + bv;
    }
}

// ===========================================================================
// Kernel 3: virtual-edge rows/cols (pure bandwidth)
// ===========================================================================
__global__ void __launch_bounds__(256) ve_kernel(
    const float4* __restrict__ vev,
    float4* __restrict__ out)
{
    const int stride = gridDim.x * 256;
    const int total = 128 * 97 * 64;
    for (int t = blockIdx.x * 256 + threadIdx.x; t < total; t += stride) {
        int d4 = t & 63;
        int r = t >> 6;
        int b = r / 97;
        int pos = r - b * 97;
        size_t cell = (size_t)b * 2401 + (pos < 49 ? pos : (size_t)(pos - 48) * 49);
        out[cell * 64 + d4] = __ldg(vev + d4);
    }
}

// ===========================================================================
// Kernel 4: interior fill, D split across warp pairs.  Warp gw handles
//   half h = gw&1 of D for a contiguous pair chunk; lane owns one float4.
//   No cross-lane ops: rstds are precomputed in g_rs.
// ===========================================================================
__device__ __forceinline__ void ld2h(const float* __restrict__ p, int dbase, U64 v[2]) {
    float4 a = __ldg((const float4*)(p + dbase));
    v[0] = f2pk(a.x, a.y); v[1] = f2pk(a.z, a.w);
}

__global__ void __launch_bounds__(128, 4) fill_kernel(
    const int4*   __restrict__ sfc,   // [B*48*48] int4
    const float4* __restrict__ sff,   // [B*48*48*2] float4
    const float*  __restrict__ gsc_p, const float* __restrict__ bsc_p,
    const float*  __restrict__ gsf_p, const float* __restrict__ bsf_ln,
    float* __restrict__ out)
{
    __shared__ __align__(16) float s_tab[44 * 256];

    const int tid = threadIdx.x;
    {
        const float4* src = (const float4*)g_tsc_c;
        float4* d4 = (float4*)s_tab;
        for (int idx = tid; idx < 44 * 64; idx += 128) d4[idx] = src[idx];
    }
    __syncthreads();

    const int lane = tid & 31;
    const int warp = tid >> 5;
    const int gw = blockIdx.x * 4 + warp;
    const int h  = gw & 1;                 // 128-float half of D
    const int wp = gw >> 1;                // pair-chunk index
    const int NP = (gridDim.x * 4) >> 1;
    const int TOT = 128 * 48 * 48;
    const int chunk = (TOT + NP - 1) / NP;
    int q = wp * chunk;
    int qend = q + chunk; if (qend > TOT) qend = TOT;
    if (q >= qend) return;

    const int dbase = h * 128 + lane * 4;  // float offset within a 256-row

    U64 gsc[2], gsf[2], bsum[2], bc2[2], wsf[8][2];
    ld2h(gsc_p, dbase, gsc);
    ld2h(gsf_p, dbase, gsf);
    {
        U64 t1[2], t2[2];
        ld2h(bsc_p, dbase, t1);
        ld2h(bsf_ln, dbase, t2);
        bsum[0] = f2add(t1[0], t2[0]);
        bsum[1] = f2add(t1[1], t2[1]);
    }
    ld2h(g_bsf_c, dbase, bc2);
#pragma unroll
    for (int f = 0; f < 8; f++) ld2h(g_wsf_c + f * 256, dbase, wsf[f]);

    const float* stab = s_tab + dbase;

    // decode q -> (b,i,j), dst
    int b = q / 2304;
    int rem = q - b * 2304;
    int i = rem / 48;
    int j = rem - i * 48;
    float* dst = out + ((size_t)((b * 49 + i + 1) * 49 + (j + 1))) * 256 + dbase;

    while (q < qend) {
        const int4   ci = __ldg(sfc + q);
        const float4 x0 = __ldg(sff + 2 * q);
        const float4 x1 = __ldg(sff + 2 * q + 1);
        const float2 rs = g_rs[q];
        if (q + 8 < TOT) {
            asm volatile("prefetch.global.L2 [%0];" :: "l"(sfc + q + 8));
            asm volatile("prefetch.global.L2 [%0];" :: "l"(sff + 2 * (q + 8)));
            asm volatile("prefetch.global.L2 [%0];" :: "l"(g_rs + q + 8));
        }

        // gather 4 centered table rows (lane's float4 slice)
        ulonglong2 a0 = *(const ulonglong2*)(stab + (ci.x + 1)  * 256);
        ulonglong2 a1 = *(const ulonglong2*)(stab + (ci.y + 12) * 256);
        ulonglong2 a2 = *(const ulonglong2*)(stab + (ci.z + 23) * 256);
        ulonglong2 a3 = *(const ulonglong2*)(stab + (ci.w + 34) * 256);
        U64 c0 = f2add(f2add(a0.x, a1.x), f2add(a2.x, a3.x));
        U64 c1 = f2add(f2add(a0.y, a1.y), f2add(a2.y, a3.y));

        // projection (centered)
        U64 p0 = bc2[0], p1 = bc2[1];
        const float xv[8] = { x0.x, x0.y, x0.z, x0.w, x1.x, x1.y, x1.z, x1.w };
#pragma unroll
        for (int f = 0; f < 8; f++) {
            U64 xd = f2dup(xv[f]);
            p0 = f2fma(wsf[f][0], xd, p0);
            p1 = f2fma(wsf[f][1], xd, p1);
        }

        const U64 rc = f2dup(rs.x), rp = f2dup(rs.y);
        U64 o0 = f2fma(c0, f2mul(gsc[0], rc), bsum[0]); o0 = f2fma(p0, f2mul(gsf[0], rp), o0);
        U64 o1 = f2fma(c1, f2mul(gsc[1], rc), bsum[1]); o1 = f2fma(p1, f2mul(gsf[1], rp), o1);

        ulonglong2 w; w.x = o0; w.y = o1;
        *(ulonglong2*)dst = w;

        // advance
        q++;
        dst += 256;
        if (++j == 48) {
            j = 0; dst += 256;
            if (++i == 48) { i = 0; dst += 49 * 256; }
        }
    }
}

// ===========================================================================
// Kernel 5: scatter-add bonds with vectorized red.global (v4.f32)
// ===========================================================================
__global__ void __launch_bounds__(128) scatter_kernel(
    const int* __restrict__ bidx,
    float* __restrict__ out)
{
    const int be = blockIdx.x;
    const int b = be >> 6, e = be & 63;
    const int t = threadIdx.x;
    const int d4 = t & 63;
    const bool fwd = t < 64;

    const int i0 = __ldg(bidx + (b * 2)     * 64 + e) + 1;
    const int i1 = __ldg(bidx + (b * 2 + 1) * 64 + e) + 1;

    const float4* src = (const float4*)(fwd ? g_hb : g_rev) + be * 64 + d4;
    const float4 v = *src;

    const size_t cell = fwd ? ((size_t)(b * 49 + i0) * 49 + i1)
                            : ((size_t)(b * 49 + i1) * 49 + i0);
    float* p = out + cell * 256 + d4 * 4;
    asm volatile("red.global.add.v4.f32 [%0], {%1, %2, %3, %4};"
                 :: "l"(p), "f"(v.x), "f"(v.y), "f"(v.z), "f"(v.w)
                 : "memory");
}

// ===========================================================================
extern "C" void kernel_launch(void* const* d_in, const int* in_sizes, int n_in,
                              void* d_out, int out_size)
{
    (void)in_sizes; (void)n_in; (void)out_size;

    const int*    bond_index = (const int*)   d_in[0];
    const int*    bfc        = (const int*)   d_in[1];
    const float*  bff        = (const float*) d_in[2];
    const float*  bmask      = (const float*) d_in[3];
    const int4*   sfc        = (const int4*)  d_in[4];
    const float4* sff        = (const float4*)d_in[5];
    const float*  tbc        = (const float*) d_in[6];
    const float*  ln_bc_g    = (const float*) d_in[7];
    const float*  ln_bc_b    = (const float*) d_in[8];
    const float*  W_bf       = (const float*) d_in[9];
    const float*  b_bf       = (const float*) d_in[10];
    const float*  ln_bf_g    = (const float*) d_in[11];
    const float*  ln_bf_b    = (const float*) d_in[12];
    const float*  tsc        = (const float*) d_in[13];
    const float*  ln_sc_g    = (const float*) d_in[14];
    const float*  ln_sc_b    = (const float*) d_in[15];
    const float*  W_sf       = (const float*) d_in[16];
    const float*  b_sf       = (const float*) d_in[17];
    const float*  ln_sf_g    = (const float*) d_in[18];
    const float*  ln_sf_b    = (const float*) d_in[19];
    const float*  ve         = (const float*) d_in[20];
    const float*  W_rev      = (const float*) d_in[21];
    const float*  b_rev      = (const float*) d_in[22];
    float* out = (float*)d_out;

    center_kernel<<<53, 256>>>(tsc, W_sf, b_sf);
    dots_kernel<<<90, 256>>>();
    rs_kernel<<<1152, 256>>>(sfc, sff);
    hb_kernel<<<8192, 256>>>(bfc, bff, bmask, tbc, ln_bc_g, ln_bc_b,
                             W_bf, b_bf, ln_bf_g, ln_bf_b);
    rev_kernel<<<512, 256>>>(W_rev, b_rev);
    ve_kernel<<<592, 256>>>((const float4*)ve, (float4*)out);
    fill_kernel<<<592, 128>>>(sfc, sff, ln_sc_g, ln_sc_b,
                              ln_sf_g, ln_sf_b, out);
    scatter_kernel<<<8192, 128>>>(bond_index, out);
}

// round 11
// speedup vs baseline: 1.2825x; 1.2016x over previous
#include <cuda_runtime.h>
#include <cstdint>

// ---------------------------------------------------------------------------
// StructureEmbeddingLayer  B=128, N=48, E=64, D=256, M=49
// ---------------------------------------------------------------------------

typedef unsigned long long U64;

// ---- packed f32x2 helpers (sm_100+) ----
__device__ __forceinline__ U64 f2pk(float lo, float hi) {
    U64 r;
    asm("mov.b64 %0, {%1, %2};" : "=l"(r)
        : "r"(__float_as_uint(lo)), "r"(__float_as_uint(hi)));
    return r;
}
__device__ __forceinline__ void f2un(U64 v, float& lo, float& hi) {
    unsigned a, b;
    asm("mov.b64 {%0, %1}, %2;" : "=r"(a), "=r"(b) : "l"(v));
    lo = __uint_as_float(a); hi = __uint_as_float(b);
}
__device__ __forceinline__ U64 f2dup(float x) { return f2pk(x, x); }
__device__ __forceinline__ U64 f2add(U64 a, U64 b) {
    U64 r; asm("add.rn.f32x2 %0, %1, %2;" : "=l"(r) : "l"(a), "l"(b)); return r;
}
__device__ __forceinline__ U64 f2mul(U64 a, U64 b) {
    U64 r; asm("mul.rn.f32x2 %0, %1, %2;" : "=l"(r) : "l"(a), "l"(b)); return r;
}
__device__ __forceinline__ U64 f2fma(U64 a, U64 b, U64 c) {
    U64 r; asm("fma.rn.f32x2 %0, %1, %2, %3;" : "=l"(r) : "l"(a), "l"(b), "l"(c)); return r;
}

__device__ __forceinline__ float warp_sum(float v) {
#pragma unroll
    for (int o = 16; o; o >>= 1) v += __shfl_xor_sync(0xffffffffu, v, o);
    return v;
}

// streaming 16B store (evict-first)
__device__ __forceinline__ void stcs2(void* p, U64 a, U64 b) {
    asm volatile("st.global.cs.v2.u64 [%0], {%1, %2};"
                 :: "l"(p), "l"(a), "l"(b) : "memory");
}

// ---- scratch (no cudaMalloc allowed) ----
__device__ float  g_hb   [8192 * 256];   // masked bond embedding  [B*E, D]
__device__ float  g_rev  [8192 * 256];   // hb @ W_rev + b_rev     [B*E, D]
__device__ float  g_tsc_c[44 * 256];     // row-centered table_sc
__device__ float  g_wsf_c[8 * 256];      // row-centered W_sf
__device__ float  g_bsf_c[256];          // centered b_sf
__device__ float  g_dotc [600];          // cross-slice dot tables (6 x 10 x 10)
__device__ float  g_norm [40];           // per-used-row squared norms
__device__ float  g_G    [64];           // W_c W_c^T (8x8)
__device__ float  g_v    [8];            // W_c . b_c
__device__ float  g_n0   [1];            // ||b_c||^2
__device__ float2 g_rs   [128 * 48 * 48]; // per-pair (rs_c, rs_p)

// ===========================================================================
// Kernel 0: center rows of table_sc / W_sf / b_sf (makes LN means exactly 0)
// ===========================================================================
__global__ void __launch_bounds__(256) center_kernel(
    const float* __restrict__ tsc, const float* __restrict__ Wsf,
    const float* __restrict__ bsf)
{
    __shared__ float red[8];
    const int blk = blockIdx.x, t = threadIdx.x;
    const float* src; float* dst;
    if (blk < 44)      { src = tsc + blk * 256;        dst = g_tsc_c + blk * 256; }
    else if (blk < 52) { src = Wsf + (blk - 44) * 256; dst = g_wsf_c + (blk - 44) * 256; }
    else               { src = bsf;                    dst = g_bsf_c; }
    float v = __ldg(src + t);
    float s = warp_sum(v);
    if ((t & 31) == 0) red[t >> 5] = s;
    __syncthreads();
    float tot = 0.f;
#pragma unroll
    for (int k = 0; k < 8; k++) tot += red[k];
    dst[t] = v - tot * (1.0f / 256.0f);
}

// ===========================================================================
// Kernel 0b: dot products for precomputed variances.
// ===========================================================================
__global__ void __launch_bounds__(256) dots_kernel()
{
    const int job = blockIdx.x * 8 + (threadIdx.x >> 5);
    const int lane = threadIdx.x & 31;
    if (job >= 713) return;
    const float *v1, *v2; float* dst;
    if (job < 600) {
        int combo = job / 100, ij = job % 100, i = ij / 10, jj = ij % 10;
        int r1, r2;
        switch (combo) {
            case 0:  r1 = 1 + i;  r2 = 12 + jj; break;   // A,B
            case 1:  r1 = 23 + i; r2 = 34 + jj; break;   // C,D
            case 2:  r1 = 1 + i;  r2 = 23 + jj; break;   // A,C
            case 3:  r1 = 1 + i;  r2 = 34 + jj; break;   // A,D
            case 4:  r1 = 12 + i; r2 = 23 + jj; break;   // B,C
            default: r1 = 12 + i; r2 = 34 + jj; break;   // B,D
        }
        v1 = g_tsc_c + r1 * 256; v2 = g_tsc_c + r2 * 256; dst = g_dotc + job;
    } else if (job < 640) {
        int jn = job - 600;
        int row = (jn / 10) * 11 + 1 + (jn % 10);
        v1 = v2 = g_tsc_c + row * 256; dst = g_norm + jn;
    } else if (job < 704) {
        int i = (job - 640) >> 3, jj = (job - 640) & 7;
        v1 = g_wsf_c + i * 256; v2 = g_wsf_c + jj * 256; dst = g_G + (job - 640);
    } else if (job < 712) {
        v1 = g_wsf_c + (job - 704) * 256; v2 = g_bsf_c; dst = g_v + (job - 704);
    } else {
        v1 = v2 = g_bsf_c; dst = g_n0;
    }
    float s = 0.f;
#pragma unroll
    for (int k = lane; k < 256; k += 32) s += v1[k] * v2[k];
    s = warp_sum(s);
    if (lane == 0) *dst = s;
}

// ===========================================================================
// Kernel 0c: per-pair rstd pre-pass + virtual-edge border writes (fused)
// ===========================================================================
__global__ void __launch_bounds__(256) rs_ve_kernel(
    const int4* __restrict__ sfc, const float4* __restrict__ sff,
    const float4* __restrict__ vev, float4* __restrict__ out)
{
    __shared__ float sQ[600];
    __shared__ float sG[64], sv2[8];
    __shared__ float sn0;
    const int t = threadIdx.x;
    for (int idx = t; idx < 600; idx += 256) {
        float val = g_dotc[idx] * 2.f;
        int combo = idx / 100, ij = idx % 100, i = ij / 10, jj = ij % 10;
        if (combo == 0)      val += g_norm[i]      + g_norm[10 + jj];
        else if (combo == 1) val += g_norm[20 + i] + g_norm[30 + jj];
        sQ[idx] = val;
    }
    if (t < 64) sG[t] = g_G[t];
    if (t < 8)  sv2[t] = 2.f * g_v[t];
    if (t == 0) sn0 = g_n0[0];
    __syncthreads();

    const int TOT = 128 * 48 * 48;
    for (int q = blockIdx.x * 256 + t; q < TOT; q += gridDim.x * 256) {
        const int4   ci = __ldg(sfc + q);
        const float4 x0 = __ldg(sff + 2 * q);
        const float4 x1 = __ldg(sff + 2 * q + 1);
        float sc = sQ[ci.x * 10 + ci.y]       + sQ[100 + ci.z * 10 + ci.w]
                 + sQ[200 + ci.x * 10 + ci.z] + sQ[300 + ci.x * 10 + ci.w]
                 + sQ[400 + ci.y * 10 + ci.z] + sQ[500 + ci.y * 10 + ci.w];
        const float xv[8] = { x0.x, x0.y, x0.z, x0.w, x1.x, x1.y, x1.z, x1.w };
        float sp = sn0;
#pragma unroll
        for (int a = 0; a < 8; a++) {
            float y = sv2[a];
#pragma unroll
            for (int b = 0; b < 8; b++) y = fmaf(sG[a * 8 + b], xv[b], y);
            sp = fmaf(xv[a], y, sp);
        }
        float2 rs;
        rs.x = rsqrtf(fmaf(sc, 1.0f / 256.0f, 1e-5f));
        rs.y = rsqrtf(fmaf(sp, 1.0f / 256.0f, 1e-5f));
        g_rs[q] = rs;
    }

    // virtual-edge border fill (independent output region)
    const int vtot = 128 * 97 * 64;
    for (int v = blockIdx.x * 256 + t; v < vtot; v += gridDim.x * 256) {
        int d4 = v & 63;
        int r = v >> 6;
        int b = r / 97;
        int pos = r - b * 97;                  // 0..48: (0,j)   49..96: (i,0)
        size_t cell = (size_t)b * 2401 + (pos < 49 ? pos : (size_t)(pos - 48) * 49);
        out[cell * 64 + d4] = __ldg(vev + d4);
    }
}

// ===========================================================================
// Kernel 1: per-bond embedding hb — warp per bond (4 bonds/warp).
//   Lane owns d = {4L..4L+3} U {128+4L..128+4L+3}. Warp-level stats only.
// ===========================================================================
__device__ __forceinline__ void ld8(const float* __restrict__ p, int lane, U64 v[4]) {
    float4 a = __ldg((const float4*)p + lane);
    float4 b = __ldg((const float4*)p + 32 + lane);
    v[0] = f2pk(a.x, a.y); v[1] = f2pk(a.z, a.w);
    v[2] = f2pk(b.x, b.y); v[3] = f2pk(b.z, b.w);
}

__global__ void __launch_bounds__(128) hb_kernel(
    const int*   __restrict__ bfc,   // [B,E,3]
    const float* __restrict__ bff,   // [B,E,4]
    const float* __restrict__ mask,  // [B,E]
    const float* __restrict__ tbc,   // [33,256]
    const float* __restrict__ g1p, const float* __restrict__ b1p,
    const float* __restrict__ Wbf,   // [4,256]
    const float* __restrict__ bbf,
    const float* __restrict__ g2p, const float* __restrict__ b2p)
{
    const int lane = threadIdx.x & 31;
    const int gw = blockIdx.x * 4 + (threadIdx.x >> 5);   // 0..2047
    const int be0 = gw * 4;

    U64 g1[4], b1[4], g2[4], b2[4], bb[4], w[4][4];
    ld8(g1p, lane, g1); ld8(b1p, lane, b1);
    ld8(g2p, lane, g2); ld8(b2p, lane, b2);
    ld8(bbf, lane, bb);
#pragma unroll
    for (int f = 0; f < 4; f++) ld8(Wbf + f * 256, lane, w[f]);

#pragma unroll
    for (int u = 0; u < 4; u++) {
        const int be = be0 + u;
        const int c0 = __ldg(bfc + be * 3 + 0) + 1;
        const int c1 = __ldg(bfc + be * 3 + 1) + 12;
        const int c2 = __ldg(bfc + be * 3 + 2) + 23;

        U64 xc[4], t0[4], t1[4];
        ld8(tbc + c0 * 256, lane, xc);
        ld8(tbc + c1 * 256, lane, t0);
        ld8(tbc + c2 * 256, lane, t1);
#pragma unroll
        for (int k = 0; k < 4; k++) xc[k] = f2add(xc[k], f2add(t0[k], t1[k]));

        const float4 xf = __ldg((const float4*)(bff + be * 4));
        U64 xp[4];
#pragma unroll
        for (int k = 0; k < 4; k++) xp[k] = bb[k];
        {
            U64 d0 = f2dup(xf.x), d1 = f2dup(xf.y), d2 = f2dup(xf.z), d3 = f2dup(xf.w);
#pragma unroll
            for (int k = 0; k < 4; k++) {
                xp[k] = f2fma(w[0][k], d0, xp[k]);
                xp[k] = f2fma(w[1][k], d1, xp[k]);
                xp[k] = f2fma(w[2][k], d2, xp[k]);
                xp[k] = f2fma(w[3][k], d3, xp[k]);
            }
        }

        // interleaved warp stats for both vectors
        U64 sC = f2add(f2add(xc[0], xc[1]), f2add(xc[2], xc[3]));
        U64 qC = f2fma(xc[0], xc[0], f2fma(xc[1], xc[1], f2fma(xc[2], xc[2], f2mul(xc[3], xc[3]))));
        U64 sP = f2add(f2add(xp[0], xp[1]), f2add(xp[2], xp[3]));
        U64 qP = f2fma(xp[0], xp[0], f2fma(xp[1], xp[1], f2fma(xp[2], xp[2], f2mul(xp[3], xp[3]))));
        float a0, a1, s_c, q_c, s_p, q_p;
        f2un(sC, a0, a1); s_c = a0 + a1;
        f2un(qC, a0, a1); q_c = a0 + a1;
        f2un(sP, a0, a1); s_p = a0 + a1;
        f2un(qP, a0, a1); q_p = a0 + a1;
#pragma unroll
        for (int o = 16; o; o >>= 1) {
            s_c += __shfl_xor_sync(0xffffffffu, s_c, o);
            q_c += __shfl_xor_sync(0xffffffffu, q_c, o);
            s_p += __shfl_xor_sync(0xffffffffu, s_p, o);
            q_p += __shfl_xor_sync(0xffffffffu, q_p, o);
        }
        const float muC = s_c * (1.0f / 256.0f);
        const float rsC = rsqrtf(fmaf(q_c, 1.0f / 256.0f, -muC * muC) + 1e-5f);
        const float muP = s_p * (1.0f / 256.0f);
        const float rsP = rsqrtf(fmaf(q_p, 1.0f / 256.0f, -muP * muP) + 1e-5f);

        const float mv = __ldg(mask + be);
        const U64 mk = f2dup(mv);
        const U64 nmC = f2dup(-muC), rC = f2dup(rsC);
        const U64 nmP = f2dup(-muP), rP = f2dup(rsP);

        float* dst = g_hb + be * 256 + lane * 4;
        U64 o0, o1;
#pragma unroll
        for (int half = 0; half < 2; half++) {
            U64 rgC0 = f2mul(g1[2 * half], rC),     rgC1 = f2mul(g1[2 * half + 1], rC);
            U64 kC0  = f2fma(rgC0, nmC, b1[2 * half]), kC1 = f2fma(rgC1, nmC, b1[2 * half + 1]);
            U64 rgP0 = f2mul(g2[2 * half], rP),     rgP1 = f2mul(g2[2 * half + 1], rP);
            U64 kP0  = f2fma(rgP0, nmP, b2[2 * half]), kP1 = f2fma(rgP1, nmP, b2[2 * half + 1]);
            o0 = f2add(f2fma(xc[2 * half], rgC0, kC0), f2fma(xp[2 * half], rgP0, kP0));
            o1 = f2add(f2fma(xc[2 * half + 1], rgC1, kC1), f2fma(xp[2 * half + 1], rgP1, kP1));
            o0 = f2mul(o0, mk); o1 = f2mul(o1, mk);
            ulonglong2 wv; wv.x = o0; wv.y = o1;
            *(ulonglong2*)(dst + half * 128) = wv;
        }
    }
}

// ===========================================================================
// Kernel 2: g_rev = g_hb @ W_rev + b_rev   (8192x256 @ 256x256)
// ===========================================================================
__global__ void __launch_bounds__(256) rev_kernel(
    const float* __restrict__ Wrev,
    const float* __restrict__ brev)
{
    constexpr int RROWS = 16, RPAD = 20;
    __shared__ __align__(16) float As[256 * RPAD];

    const int row0 = blockIdx.x * RROWS;
    const int t = threadIdx.x;

    for (int idx = t; idx < 256 * RROWS; idx += 256) {
        int r = idx >> 8;
        int k = idx & 255;
        As[k * RPAD + r] = g_hb[(row0 + r) * 256 + k];
    }
    __syncthreads();

    U64 acc[8];
#pragma unroll
    for (int p = 0; p < 8; p++) acc[p] = 0ULL;

#pragma unroll 4
    for (int k = 0; k < 256; k++) {
        U64 wd = f2dup(__ldg(Wrev + k * 256 + t));
        const ulonglong2* ap = (const ulonglong2*)(As + k * RPAD);
#pragma unroll
        for (int q = 0; q < 4; q++) {
            ulonglong2 a = ap[q];
            acc[2 * q]     = f2fma(a.x, wd, acc[2 * q]);
            acc[2 * q + 1] = f2fma(a.y, wd, acc[2 * q + 1]);
        }
    }

    const float bv = __ldg(brev + t);
#pragma unroll
    for (int p = 0; p < 8; p++) {
        float lo, hi; f2un(acc[p], lo, hi);
        g_rev[(row0 + 2 * p)     * 256 + t] = lo + bv;
        g_rev[(row0 + 2 * p + 1) * 256 + t] = hi + bv;
    }
}

// ===========================================================================
// Kernel 3: interior fill — ONE warp per pair, no cross-lane ops.
//   Lane owns d = {4L..4L+3} U {128+4L..128+4L+3}. Streaming stores.
// ===========================================================================
__global__ void __launch_bounds__(128, 3) fill_kernel(
    const int4*   __restrict__ sfc,   // [B*48*48] int4
    const float4* __restrict__ sff,   // [B*48*48*2] float4
    const float*  __restrict__ gsc_p, const float* __restrict__ bsc_p,
    const float*  __restrict__ gsf_p, const float* __restrict__ bsf_ln,
    float* __restrict__ out)
{
    __shared__ __align__(16) float s_tab[44 * 256];

    const int tid = threadIdx.x;
    {
        const float4* src = (const float4*)g_tsc_c;
        float4* d4 = (float4*)s_tab;
        for (int idx = tid; idx < 44 * 64; idx += 128) d4[idx] = src[idx];
    }
    __syncthreads();

    const int lane = tid & 31;
    const int warp = tid >> 5;

    U64 gsc[4], gsf[4], bsum[4], bc[4], wsf[8][4];
    ld8(gsc_p, lane, gsc);
    ld8(gsf_p, lane, gsf);
    {
        U64 t1[4], t2[4];
        ld8(bsc_p, lane, t1);
        ld8(bsf_ln, lane, t2);
#pragma unroll
        for (int p = 0; p < 4; p++) bsum[p] = f2add(t1[p], t2[p]);
    }
    ld8(g_bsf_c, lane, bc);
#pragma unroll
    for (int f = 0; f < 8; f++) ld8(g_wsf_c + f * 256, lane, wsf[f]);

    const float* stabA = s_tab + lane * 4;
    const float* stabB = s_tab + 128 + lane * 4;

    const int TOT = 128 * 48 * 48;
    const int NW = gridDim.x * 4;
    const int gw = blockIdx.x * 4 + warp;
    const int chunk = (TOT + NW - 1) / NW;
    int q = gw * chunk;
    int qend = q + chunk; if (qend > TOT) qend = TOT;
    if (q >= qend) return;

    int b = q / 2304;
    int rem = q - b * 2304;
    int i = rem / 48;
    int j = rem - i * 48;
    float* dst = out + ((size_t)((b * 49 + i + 1) * 49 + (j + 1))) * 256 + lane * 4;

    while (q < qend) {
        const int4   ci = __ldg(sfc + q);
        const float4 x0 = __ldg(sff + 2 * q);
        const float4 x1 = __ldg(sff + 2 * q + 1);
        const float2 rs = __ldg((const float2*)g_rs + q);

        const int r0 = (ci.x + 1)  * 256;
        const int r1 = (ci.y + 12) * 256;
        const int r2 = (ci.z + 23) * 256;
        const int r3 = (ci.w + 34) * 256;

        // gather 4 centered table rows, both 128-halves
        ulonglong2 a0 = *(const ulonglong2*)(stabA + r0);
        ulonglong2 a1 = *(const ulonglong2*)(stabA + r1);
        ulonglong2 a2 = *(const ulonglong2*)(stabA + r2);
        ulonglong2 a3 = *(const ulonglong2*)(stabA + r3);
        U64 c0 = f2add(f2add(a0.x, a1.x), f2add(a2.x, a3.x));
        U64 c1 = f2add(f2add(a0.y, a1.y), f2add(a2.y, a3.y));
        a0 = *(const ulonglong2*)(stabB + r0);
        a1 = *(const ulonglong2*)(stabB + r1);
        a2 = *(const ulonglong2*)(stabB + r2);
        a3 = *(const ulonglong2*)(stabB + r3);
        U64 c2 = f2add(f2add(a0.x, a1.x), f2add(a2.x, a3.x));
        U64 c3 = f2add(f2add(a0.y, a1.y), f2add(a2.y, a3.y));

        // centered projection
        U64 p0 = bc[0], p1 = bc[1], p2 = bc[2], p3 = bc[3];
        const float xv[8] = { x0.x, x0.y, x0.z, x0.w, x1.x, x1.y, x1.z, x1.w };
#pragma unroll
        for (int f = 0; f < 8; f++) {
            U64 xd = f2dup(xv[f]);
            p0 = f2fma(wsf[f][0], xd, p0);
            p1 = f2fma(wsf[f][1], xd, p1);
            p2 = f2fma(wsf[f][2], xd, p2);
            p3 = f2fma(wsf[f][3], xd, p3);
        }

        const U64 rc = f2dup(rs.x), rp = f2dup(rs.y);
        U64 o0 = f2fma(c0, f2mul(gsc[0], rc), bsum[0]); o0 = f2fma(p0, f2mul(gsf[0], rp), o0);
        U64 o1 = f2fma(c1, f2mul(gsc[1], rc), bsum[1]); o1 = f2fma(p1, f2mul(gsf[1], rp), o1);
        U64 o2 = f2fma(c2, f2mul(gsc[2], rc), bsum[2]); o2 = f2fma(p2, f2mul(gsf[2], rp), o2);
        U64 o3 = f2fma(c3, f2mul(gsc[3], rc), bsum[3]); o3 = f2fma(p3, f2mul(gsf[3], rp), o3);

        stcs2(dst,       o0, o1);
        stcs2(dst + 128, o2, o3);

        q++;
        dst += 256;
        if (++j == 48) {
            j = 0; dst += 256;
            if (++i == 48) { i = 0; dst += 49 * 256; }
        }
    }
}

// ===========================================================================
// Kernel 4: scatter-add bonds with vectorized red.global (v4.f32)
// ===========================================================================
__global__ void __launch_bounds__(128) scatter_kernel(
    const int* __restrict__ bidx,
    float* __restrict__ out)
{
    const int be = blockIdx.x;
    const int b = be >> 6, e = be & 63;
    const int t = threadIdx.x;
    const int d4 = t & 63;
    const bool fwd = t < 64;

    const int i0 = __ldg(bidx + (b * 2)     * 64 + e) + 1;
    const int i1 = __ldg(bidx + (b * 2 + 1) * 64 + e) + 1;

    const float4* src = (const float4*)(fwd ? g_hb : g_rev) + be * 64 + d4;
    const float4 v = *src;

    const size_t cell = fwd ? ((size_t)(b * 49 + i0) * 49 + i1)
                            : ((size_t)(b * 49 + i1) * 49 + i0);
    float* p = out + cell * 256 + d4 * 4;
    asm volatile("red.global.add.v4.f32 [%0], {%1, %2, %3, %4};"
                 :: "l"(p), "f"(v.x), "f"(v.y), "f"(v.z), "f"(v.w)
                 : "memory");
}

// ===========================================================================
extern "C" void kernel_launch(void* const* d_in, const int* in_sizes, int n_in,
                              void* d_out, int out_size)
{
    (void)in_sizes; (void)n_in; (void)out_size;

    const int*    bond_index = (const int*)   d_in[0];
    const int*    bfc        = (const int*)   d_in[1];
    const float*  bff        = (const float*) d_in[2];
    const float*  bmask      = (const float*) d_in[3];
    const int4*   sfc        = (const int4*)  d_in[4];
    const float4* sff        = (const float4*)d_in[5];
    const float*  tbc        = (const float*) d_in[6];
    const float*  ln_bc_g    = (const float*) d_in[7];
    const float*  ln_bc_b    = (const float*) d_in[8];
    const float*  W_bf       = (const float*) d_in[9];
    const float*  b_bf       = (const float*) d_in[10];
    const float*  ln_bf_g    = (const float*) d_in[11];
    const float*  ln_bf_b    = (const float*) d_in[12];
    const float*  tsc        = (const float*) d_in[13];
    const float*  ln_sc_g    = (const float*) d_in[14];
    const float*  ln_sc_b    = (const float*) d_in[15];
    const float*  W_sf       = (const float*) d_in[16];
    const float*  b_sf       = (const float*) d_in[17];
    const float*  ln_sf_g    = (const float*) d_in[18];
    const float*  ln_sf_b    = (const float*) d_in[19];
    const float*  ve         = (const float*) d_in[20];
    const float*  W_rev      = (const float*) d_in[21];
    const float*  b_rev      = (const float*) d_in[22];
    float* out = (float*)d_out;

    center_kernel<<<53, 256>>>(tsc, W_sf, b_sf);
    dots_kernel<<<90, 256>>>();
    rs_ve_kernel<<<1152, 256>>>(sfc, sff, (const float4*)ve, (float4*)out);
    hb_kernel<<<512, 128>>>(bfc, bff, bmask, tbc, ln_bc_g, ln_bc_b,
                            W_bf, b_bf, ln_bf_g, ln_bf_b);
    rev_kernel<<<512, 256>>>(W_rev, b_rev);
    fill_kernel<<<444, 128>>>(sfc, sff, ln_sc_g, ln_sc_b,
                              ln_sf_g, ln_sf_b, out);
    scatter_kernel<<<8192, 128>>>(bond_index, out);
}

// round 12
// speedup vs baseline: 1.3554x; 1.0569x over previous
#include <cuda_runtime.h>
#include <cstdint>

// ---------------------------------------------------------------------------
// StructureEmbeddingLayer  B=128, N=48, E=64, D=256, M=49
// ---------------------------------------------------------------------------

typedef unsigned long long U64;

// ---- packed f32x2 helpers (sm_100+) ----
__device__ __forceinline__ U64 f2pk(float lo, float hi) {
    U64 r;
    asm("mov.b64 %0, {%1, %2};" : "=l"(r)
        : "r"(__float_as_uint(lo)), "r"(__float_as_uint(hi)));
    return r;
}
__device__ __forceinline__ void f2un(U64 v, float& lo, float& hi) {
    unsigned a, b;
    asm("mov.b64 {%0, %1}, %2;" : "=r"(a), "=r"(b) : "l"(v));
    lo = __uint_as_float(a); hi = __uint_as_float(b);
}
__device__ __forceinline__ U64 f2dup(float x) { return f2pk(x, x); }
__device__ __forceinline__ U64 f2add(U64 a, U64 b) {
    U64 r; asm("add.rn.f32x2 %0, %1, %2;" : "=l"(r) : "l"(a), "l"(b)); return r;
}
__device__ __forceinline__ U64 f2mul(U64 a, U64 b) {
    U64 r; asm("mul.rn.f32x2 %0, %1, %2;" : "=l"(r) : "l"(a), "l"(b)); return r;
}
__device__ __forceinline__ U64 f2fma(U64 a, U64 b, U64 c) {
    U64 r; asm("fma.rn.f32x2 %0, %1, %2, %3;" : "=l"(r) : "l"(a), "l"(b), "l"(c)); return r;
}

__device__ __forceinline__ float warp_sum(float v) {
#pragma unroll
    for (int o = 16; o; o >>= 1) v += __shfl_xor_sync(0xffffffffu, v, o);
    return v;
}

// streaming 16B store (evict-first)
__device__ __forceinline__ void stcs2(void* p, U64 a, U64 b) {
    asm volatile("st.global.cs.v2.u64 [%0], {%1, %2};"
                 :: "l"(p), "l"(a), "l"(b) : "memory");
}

// ---- scratch (no cudaMalloc allowed) ----
__device__ float  g_hb   [8192 * 256];   // masked bond embedding  [B*E, D]
__device__ float  g_rev  [8192 * 256];   // hb @ W_rev + b_rev     [B*E, D]
__device__ float  g_tsc_c[44 * 256];     // row-centered table_sc
__device__ float  g_wsf_c[8 * 256];      // row-centered W_sf
__device__ float  g_bsf_c[256];          // centered b_sf
__device__ float  g_wp   [8 * 256];      // W' = centered W_sf * gamma_sf
__device__ float  g_bp   [256];          // b' = centered b_sf * gamma_sf
__device__ float  g_dotc [600];          // cross-slice dot tables (6 x 10 x 10)
__device__ float  g_norm [40];           // per-used-row squared norms
__device__ float  g_G    [64];           // W_c W_c^T (8x8)
__device__ float  g_v    [8];            // W_c . b_c
__device__ float  g_n0   [1];            // ||b_c||^2
__device__ float2 g_rs   [128 * 48 * 48];// per-pair (combo-as-int-bits, rs_p)
__device__ float  g_T    [10000 * 256];  // LN-applied cate row per combo (+bias)

// ===========================================================================
// Kernel 0: center rows of table_sc / W_sf / b_sf (makes LN means exactly 0)
// ===========================================================================
__global__ void __launch_bounds__(256) center_kernel(
    const float* __restrict__ tsc, const float* __restrict__ Wsf,
    const float* __restrict__ bsf)
{
    __shared__ float red[8];
    const int blk = blockIdx.x, t = threadIdx.x;
    const float* src; float* dst;
    if (blk < 44)      { src = tsc + blk * 256;        dst = g_tsc_c + blk * 256; }
    else if (blk < 52) { src = Wsf + (blk - 44) * 256; dst = g_wsf_c + (blk - 44) * 256; }
    else               { src = bsf;                    dst = g_bsf_c; }
    float v = __ldg(src + t);
    float s = warp_sum(v);
    if ((t & 31) == 0) red[t >> 5] = s;
    __syncthreads();
    float tot = 0.f;
#pragma unroll
    for (int k = 0; k < 8; k++) tot += red[k];
    dst[t] = v - tot * (1.0f / 256.0f);
}

// ===========================================================================
// Kernel 0a: pre-scale projection weights by gamma_sf
// ===========================================================================
__global__ void __launch_bounds__(256) prep2_kernel(const float* __restrict__ gsf)
{
    const int blk = blockIdx.x, t = threadIdx.x;
    const float gv = __ldg(gsf + t);
    if (blk < 8) g_wp[blk * 256 + t] = g_wsf_c[blk * 256 + t] * gv;
    else         g_bp[t]             = g_bsf_c[t] * gv;
}

// ===========================================================================
// Kernel 0b: dot products for precomputed variances.
// ===========================================================================
__global__ void __launch_bounds__(256) dots_kernel()
{
    const int job = blockIdx.x * 8 + (threadIdx.x >> 5);
    const int lane = threadIdx.x & 31;
    if (job >= 713) return;
    const float *v1, *v2; float* dst;
    if (job < 600) {
        int combo = job / 100, ij = job % 100, i = ij / 10, jj = ij % 10;
        int r1, r2;
        switch (combo) {
            case 0:  r1 = 1 + i;  r2 = 12 + jj; break;   // A,B
            case 1:  r1 = 23 + i; r2 = 34 + jj; break;   // C,D
            case 2:  r1 = 1 + i;  r2 = 23 + jj; break;   // A,C
            case 3:  r1 = 1 + i;  r2 = 34 + jj; break;   // A,D
            case 4:  r1 = 12 + i; r2 = 23 + jj; break;   // B,C
            default: r1 = 12 + i; r2 = 34 + jj; break;   // B,D
        }
        v1 = g_tsc_c + r1 * 256; v2 = g_tsc_c + r2 * 256; dst = g_dotc + job;
    } else if (job < 640) {
        int jn = job - 600;
        int row = (jn / 10) * 11 + 1 + (jn % 10);
        v1 = v2 = g_tsc_c + row * 256; dst = g_norm + jn;
    } else if (job < 704) {
        int i = (job - 640) >> 3, jj = (job - 640) & 7;
        v1 = g_wsf_c + i * 256; v2 = g_wsf_c + jj * 256; dst = g_G + (job - 640);
    } else if (job < 712) {
        v1 = g_wsf_c + (job - 704) * 256; v2 = g_bsf_c; dst = g_v + (job - 704);
    } else {
        v1 = v2 = g_bsf_c; dst = g_n0;
    }
    float s = 0.f;
#pragma unroll
    for (int k = lane; k < 256; k += 32) s += v1[k] * v2[k];
    s = warp_sum(s);
    if (lane == 0) *dst = s;
}

// ---- common: per-lane 8-float loads (d = {4L..4L+3} U {128+4L..128+4L+3}) ----
__device__ __forceinline__ void ld8(const float* __restrict__ p, int lane, U64 v[4]) {
    float4 a = __ldg((const float4*)p + lane);
    float4 b = __ldg((const float4*)p + 32 + lane);
    v[0] = f2pk(a.x, a.y); v[1] = f2pk(a.z, a.w);
    v[2] = f2pk(b.x, b.y); v[3] = f2pk(b.z, b.w);
}

// ===========================================================================
// Kernel 0c: per-combo LN-applied cate table T[combo][d]
//   T = (b_sc + b_sf_ln) + gamma_sc * rs_c(combo) * sum of 4 centered rows
//   One warp per combo, grid 2500 x 128.
// ===========================================================================
__global__ void __launch_bounds__(128) tbl_kernel(
    const float* __restrict__ gsc_p, const float* __restrict__ bsc_p,
    const float* __restrict__ bsf_ln)
{
    __shared__ float sQ[600];
    const int t = threadIdx.x;
    for (int idx = t; idx < 600; idx += 128) {
        float val = g_dotc[idx] * 2.f;
        int combo = idx / 100, ij = idx % 100, i = ij / 10, jj = ij % 10;
        if (combo == 0)      val += g_norm[i]      + g_norm[10 + jj];
        else if (combo == 1) val += g_norm[20 + i] + g_norm[30 + jj];
        sQ[idx] = val;
    }
    __syncthreads();

    const int lane = t & 31;
    const int combo = blockIdx.x * 4 + (t >> 5);
    if (combo >= 10000) return;

    int r = combo;
    const int a  = r / 1000; r -= a * 1000;
    const int bb = r / 100;  r -= bb * 100;
    const int cc = r / 10;
    const int dd = r - cc * 10;

    const float sc = sQ[a * 10 + bb]       + sQ[100 + cc * 10 + dd]
                   + sQ[200 + a * 10 + cc] + sQ[300 + a * 10 + dd]
                   + sQ[400 + bb * 10 + cc] + sQ[500 + bb * 10 + dd];
    const float rs_c = rsqrtf(fmaf(sc, 1.0f / 256.0f, 1e-5f));
    const U64 rc = f2dup(rs_c);

    U64 gsc[4], bsum[4];
    ld8(gsc_p, lane, gsc);
    {
        U64 t1[4], t2[4];
        ld8(bsc_p, lane, t1);
        ld8(bsf_ln, lane, t2);
#pragma unroll
        for (int k = 0; k < 4; k++) bsum[k] = f2add(t1[k], t2[k]);
    }

    U64 c[4], u0[4], u1[4], u2[4];
    ld8(g_tsc_c + (a + 1)  * 256, lane, c);
    ld8(g_tsc_c + (bb + 12) * 256, lane, u0);
    ld8(g_tsc_c + (cc + 23) * 256, lane, u1);
    ld8(g_tsc_c + (dd + 34) * 256, lane, u2);
#pragma unroll
    for (int k = 0; k < 4; k++)
        c[k] = f2add(f2add(c[k], u0[k]), f2add(u1[k], u2[k]));

    U64 o[4];
#pragma unroll
    for (int k = 0; k < 4; k++) o[k] = f2fma(c[k], f2mul(gsc[k], rc), bsum[k]);

    float* dst = g_T + combo * 256 + lane * 4;
    ulonglong2 w0; w0.x = o[0]; w0.y = o[1];
    ulonglong2 w1; w1.x = o[2]; w1.y = o[3];
    *(ulonglong2*)dst         = w0;
    *(ulonglong2*)(dst + 128) = w1;
}

// ===========================================================================
// Kernel 0d: per-pair (combo, rs_p) pre-pass + virtual-edge border writes
// ===========================================================================
__global__ void __launch_bounds__(256) rs_ve_kernel(
    const int4* __restrict__ sfc, const float4* __restrict__ sff,
    const float4* __restrict__ vev, float4* __restrict__ out)
{
    __shared__ float sG[64], sv2[8];
    __shared__ float sn0;
    const int t = threadIdx.x;
    if (t < 64) sG[t] = g_G[t];
    if (t < 8)  sv2[t] = 2.f * g_v[t];
    if (t == 0) sn0 = g_n0[0];
    __syncthreads();

    const int TOT = 128 * 48 * 48;
    for (int q = blockIdx.x * 256 + t; q < TOT; q += gridDim.x * 256) {
        const int4   ci = __ldg(sfc + q);
        const float4 x0 = __ldg(sff + 2 * q);
        const float4 x1 = __ldg(sff + 2 * q + 1);
        const int combo = ((ci.x * 10 + ci.y) * 10 + ci.z) * 10 + ci.w;
        const float xv[8] = { x0.x, x0.y, x0.z, x0.w, x1.x, x1.y, x1.z, x1.w };
        float sp = sn0;
#pragma unroll
        for (int a = 0; a < 8; a++) {
            float y = sv2[a];
#pragma unroll
            for (int b = 0; b < 8; b++) y = fmaf(sG[a * 8 + b], xv[b], y);
            sp = fmaf(xv[a], y, sp);
        }
        float2 meta;
        meta.x = __int_as_float(combo);
        meta.y = rsqrtf(fmaf(sp, 1.0f / 256.0f, 1e-5f));
        g_rs[q] = meta;
    }

    // virtual-edge border fill (disjoint output region)
    const int vtot = 128 * 97 * 64;
    for (int v = blockIdx.x * 256 + t; v < vtot; v += gridDim.x * 256) {
        int d4 = v & 63;
        int r = v >> 6;
        int b = r / 97;
        int pos = r - b * 97;                  // 0..48: (0,j)   49..96: (i,0)
        size_t cell = (size_t)b * 2401 + (pos < 49 ? pos : (size_t)(pos - 48) * 49);
        out[cell * 64 + d4] = __ldg(vev + d4);
    }
}

// ===========================================================================
// Kernel 1: per-bond embedding hb — warp per 2 bonds (grid 1024 x 128)
// ===========================================================================
__global__ void __launch_bounds__(128) hb_kernel(
    const int*   __restrict__ bfc,   // [B,E,3]
    const float* __restrict__ bff,   // [B,E,4]
    const float* __restrict__ mask,  // [B,E]
    const float* __restrict__ tbc,   // [33,256]
    const float* __restrict__ g1p, const float* __restrict__ b1p,
    const float* __restrict__ Wbf,   // [4,256]
    const float* __restrict__ bbf,
    const float* __restrict__ g2p, const float* __restrict__ b2p)
{
    const int lane = threadIdx.x & 31;
    const int gw = blockIdx.x * 4 + (threadIdx.x >> 5);   // 0..4095
    const int be0 = gw * 2;

    U64 g1[4], b1[4], g2[4], b2[4], bb[4], w[4][4];
    ld8(g1p, lane, g1); ld8(b1p, lane, b1);
    ld8(g2p, lane, g2); ld8(b2p, lane, b2);
    ld8(bbf, lane, bb);
#pragma unroll
    for (int f = 0; f < 4; f++) ld8(Wbf + f * 256, lane, w[f]);

#pragma unroll
    for (int u = 0; u < 2; u++) {
        const int be = be0 + u;
        const int c0 = __ldg(bfc + be * 3 + 0) + 1;
        const int c1 = __ldg(bfc + be * 3 + 1) + 12;
        const int c2 = __ldg(bfc + be * 3 + 2) + 23;

        U64 xc[4], t0[4], t1[4];
        ld8(tbc + c0 * 256, lane, xc);
        ld8(tbc + c1 * 256, lane, t0);
        ld8(tbc + c2 * 256, lane, t1);
#pragma unroll
        for (int k = 0; k < 4; k++) xc[k] = f2add(xc[k], f2add(t0[k], t1[k]));

        const float4 xf = __ldg((const float4*)(bff + be * 4));
        U64 xp[4];
#pragma unroll
        for (int k = 0; k < 4; k++) xp[k] = bb[k];
        {
            U64 d0 = f2dup(xf.x), d1 = f2dup(xf.y), d2 = f2dup(xf.z), d3 = f2dup(xf.w);
#pragma unroll
            for (int k = 0; k < 4; k++) {
                xp[k] = f2fma(w[0][k], d0, xp[k]);
                xp[k] = f2fma(w[1][k], d1, xp[k]);
                xp[k] = f2fma(w[2][k], d2, xp[k]);
                xp[k] = f2fma(w[3][k], d3, xp[k]);
            }
        }

        U64 sC = f2add(f2add(xc[0], xc[1]), f2add(xc[2], xc[3]));
        U64 qC = f2fma(xc[0], xc[0], f2fma(xc[1], xc[1], f2fma(xc[2], xc[2], f2mul(xc[3], xc[3]))));
        U64 sP = f2add(f2add(xp[0], xp[1]), f2add(xp[2], xp[3]));
        U64 qP = f2fma(xp[0], xp[0], f2fma(xp[1], xp[1], f2fma(xp[2], xp[2], f2mul(xp[3], xp[3]))));
        float a0, a1, s_c, q_c, s_p, q_p;
        f2un(sC, a0, a1); s_c = a0 + a1;
        f2un(qC, a0, a1); q_c = a0 + a1;
        f2un(sP, a0, a1); s_p = a0 + a1;
        f2un(qP, a0, a1); q_p = a0 + a1;
#pragma unroll
        for (int o = 16; o; o >>= 1) {
            s_c += __shfl_xor_sync(0xffffffffu, s_c, o);
            q_c += __shfl_xor_sync(0xffffffffu, q_c, o);
            s_p += __shfl_xor_sync(0xffffffffu, s_p, o);
            q_p += __shfl_xor_sync(0xffffffffu, q_p, o);
        }
        const float muC = s_c * (1.0f / 256.0f);
        const float rsC = rsqrtf(fmaf(q_c, 1.0f / 256.0f, -muC * muC) + 1e-5f);
        const float muP = s_p * (1.0f / 256.0f);
        const float rsP = rsqrtf(fmaf(q_p, 1.0f / 256.0f, -muP * muP) + 1e-5f);

        const float mv = __ldg(mask + be);
        const U64 mk = f2dup(mv);
        const U64 nmC = f2dup(-muC), rC = f2dup(rsC);
        const U64 nmP = f2dup(-muP), rP = f2dup(rsP);

        float* dst = g_hb + be * 256 + lane * 4;
#pragma unroll
        for (int half = 0; half < 2; half++) {
            U64 rgC0 = f2mul(g1[2 * half], rC),     rgC1 = f2mul(g1[2 * half + 1], rC);
            U64 kC0  = f2fma(rgC0, nmC, b1[2 * half]), kC1 = f2fma(rgC1, nmC, b1[2 * half + 1]);
            U64 rgP0 = f2mul(g2[2 * half], rP),     rgP1 = f2mul(g2[2 * half + 1], rP);
            U64 kP0  = f2fma(rgP0, nmP, b2[2 * half]), kP1 = f2fma(rgP1, nmP, b2[2 * half + 1]);
            U64 o0 = f2add(f2fma(xc[2 * half], rgC0, kC0), f2fma(xp[2 * half], rgP0, kP0));
            U64 o1 = f2add(f2fma(xc[2 * half + 1], rgC1, kC1), f2fma(xp[2 * half + 1], rgP1, kP1));
            o0 = f2mul(o0, mk); o1 = f2mul(o1, mk);
            ulonglong2 wv; wv.x = o0; wv.y = o1;
            *(ulonglong2*)(dst + half * 128) = wv;
        }
    }
}

// ===========================================================================
// Kernel 2: g_rev = g_hb @ W_rev + b_rev   (8192x256 @ 256x256)
// ===========================================================================
__global__ void __launch_bounds__(256) rev_kernel(
    const float* __restrict__ Wrev,
    const float* __restrict__ brev)
{
    constexpr int RROWS = 16, RPAD = 20;
    __shared__ __align__(16) float As[256 * RPAD];

    const int row0 = blockIdx.x * RROWS;
    const int t = threadIdx.x;

    for (int idx = t; idx < 256 * RROWS; idx += 256) {
        int r = idx >> 8;
        int k = idx & 255;
        As[k * RPAD + r] = g_hb[(row0 + r) * 256 + k];
    }
    __syncthreads();

    U64 acc[8];
#pragma unroll
    for (int p = 0; p < 8; p++) acc[p] = 0ULL;

#pragma unroll 4
    for (int k = 0; k < 256; k++) {
        U64 wd = f2dup(__ldg(Wrev + k * 256 + t));
        const ulonglong2* ap = (const ulonglong2*)(As + k * RPAD);
#pragma unroll
        for (int q = 0; q < 4; q++) {
            ulonglong2 a = ap[q];
            acc[2 * q]     = f2fma(a.x, wd, acc[2 * q]);
            acc[2 * q + 1] = f2fma(a.y, wd, acc[2 * q + 1]);
        }
    }

    const float bv = __ldg(brev + t);
#pragma unroll
    for (int p = 0; p < 8; p++) {
        float lo, hi; f2un(acc[p], lo, hi);
        g_rev[(row0 + 2 * p)     * 256 + t] = lo + bv;
        g_rev[(row0 + 2 * p + 1) * 256 + t] = hi + bv;
    }
}

// ===========================================================================
// Kernel 3: interior fill — warp per pair, NO smem, NO cate math.
//   out = T[combo] + rs_p * (b' + W'^T x).  Streaming stores.
// ===========================================================================
__global__ void __launch_bounds__(128, 4) fill_kernel(
    const float4* __restrict__ sff,   // [B*48*48*2] float4
    float* __restrict__ out)
{
    const int lane = threadIdx.x & 31;
    const int warp = threadIdx.x >> 5;

    U64 wp[8][4], bp[4];
#pragma unroll
    for (int f = 0; f < 8; f++) ld8(g_wp + f * 256, lane, wp[f]);
    ld8(g_bp, lane, bp);

    const int TOT = 128 * 48 * 48;
    const int NW = gridDim.x * 4;
    const int gw = blockIdx.x * 4 + warp;
    const int chunk = (TOT + NW - 1) / NW;
    int q = gw * chunk;
    int qend = q + chunk; if (qend > TOT) qend = TOT;
    if (q >= qend) return;

    int b = q / 2304;
    int rem = q - b * 2304;
    int i = rem / 48;
    int j = rem - i * 48;
    float* dst = out + ((size_t)((b * 49 + i + 1) * 49 + (j + 1))) * 256 + lane * 4;

    while (q < qend) {
        const float2 meta = __ldg((const float2*)g_rs + q);
        const int combo = __float_as_int(meta.x);
        const float4 x0 = __ldg(sff + 2 * q);
        const float4 x1 = __ldg(sff + 2 * q + 1);

        const float* Tr = g_T + combo * 256 + lane * 4;
        const float4 t0 = __ldg((const float4*)Tr);
        const float4 t1 = __ldg((const float4*)(Tr + 128));

        U64 p0 = bp[0], p1 = bp[1], p2 = bp[2], p3 = bp[3];
        const float xv[8] = { x0.x, x0.y, x0.z, x0.w, x1.x, x1.y, x1.z, x1.w };
#pragma unroll
        for (int f = 0; f < 8; f++) {
            U64 xd = f2dup(xv[f]);
            p0 = f2fma(wp[f][0], xd, p0);
            p1 = f2fma(wp[f][1], xd, p1);
            p2 = f2fma(wp[f][2], xd, p2);
            p3 = f2fma(wp[f][3], xd, p3);
        }

        const U64 rp = f2dup(meta.y);
        U64 o0 = f2fma(p0, rp, f2pk(t0.x, t0.y));
        U64 o1 = f2fma(p1, rp, f2pk(t0.z, t0.w));
        U64 o2 = f2fma(p2, rp, f2pk(t1.x, t1.y));
        U64 o3 = f2fma(p3, rp, f2pk(t1.z, t1.w));

        stcs2(dst,       o0, o1);
        stcs2(dst + 128, o2, o3);

        q++;
        dst += 256;
        if (++j == 48) {
            j = 0; dst += 256;
            if (++i == 48) { i = 0; dst += 49 * 256; }
        }
    }
}

// ===========================================================================
// Kernel 4: scatter-add bonds with vectorized red.global (v4.f32)
// ===========================================================================
__global__ void __launch_bounds__(128) scatter_kernel(
    const int* __restrict__ bidx,
    float* __restrict__ out)
{
    const int be = blockIdx.x;
    const int b = be >> 6, e = be & 63;
    const int t = threadIdx.x;
    const int d4 = t & 63;
    const bool fwd = t < 64;

    const int i0 = __ldg(bidx + (b * 2)     * 64 + e) + 1;
    const int i1 = __ldg(bidx + (b * 2 + 1) * 64 + e) + 1;

    const float4* src = (const float4*)(fwd ? g_hb : g_rev) + be * 64 + d4;
    const float4 v = *src;

    const size_t cell = fwd ? ((size_t)(b * 49 + i0) * 49 + i1)
                            : ((size_t)(b * 49 + i1) * 49 + i0);
    float* p = out + cell * 256 + d4 * 4;
    asm volatile("red.global.add.v4.f32 [%0], {%1, %2, %3, %4};"
                 :: "l"(p), "f"(v.x), "f"(v.y), "f"(v.z), "f"(v.w)
                 : "memory");
}

// ===========================================================================
extern "C" void kernel_launch(void* const* d_in, const int* in_sizes, int n_in,
                              void* d_out, int out_size)
{
    (void)in_sizes; (void)n_in; (void)out_size;

    const int*    bond_index = (const int*)   d_in[0];
    const int*    bfc        = (const int*)   d_in[1];
    const float*  bff        = (const float*) d_in[2];
    const float*  bmask      = (const float*) d_in[3];
    const int4*   sfc        = (const int4*)  d_in[4];
    const float4* sff        = (const float4*)d_in[5];
    const float*  tbc        = (const float*) d_in[6];
    const float*  ln_bc_g    = (const float*) d_in[7];
    const float*  ln_bc_b    = (const float*) d_in[8];
    const float*  W_bf       = (const float*) d_in[9];
    const float*  b_bf       = (const float*) d_in[10];
    const float*  ln_bf_g    = (const float*) d_in[11];
    const float*  ln_bf_b    = (const float*) d_in[12];
    const float*  tsc        = (const float*) d_in[13];
    const float*  ln_sc_g    = (const float*) d_in[14];
    const float*  ln_sc_b    = (const float*) d_in[15];
    const float*  W_sf       = (const float*) d_in[16];
    const float*  b_sf       = (const float*) d_in[17];
    const float*  ln_sf_g    = (const float*) d_in[18];
    const float*  ln_sf_b    = (const float*) d_in[19];
    const float*  ve         = (const float*) d_in[20];
    const float*  W_rev      = (const float*) d_in[21];
    const float*  b_rev      = (const float*) d_in[22];
    float* out = (float*)d_out;

    center_kernel<<<53, 256>>>(tsc, W_sf, b_sf);
    prep2_kernel<<<9, 256>>>(ln_sf_g);
    dots_kernel<<<90, 256>>>();
    tbl_kernel<<<2500, 128>>>(ln_sc_g, ln_sc_b, ln_sf_b);
    rs_ve_kernel<<<1152, 256>>>(sfc, sff, (const float4*)ve, (float4*)out);
    hb_kernel<<<1024, 128>>>(bfc, bff, bmask, tbc, ln_bc_g, ln_bc_b,
                             W_bf, b_bf, ln_bf_g, ln_bf_b);
    rev_kernel<<<512, 256>>>(W_rev, b_rev);
    fill_kernel<<<592, 128>>>(sff, out);
    scatter_kernel<<<8192, 128>>>(bond_index, out);
}